// round 15
// baseline (speedup 1.0000x reference)
#include <cuda_runtime.h>
#include <cuda_bf16.h>
#include <cuda_fp16.h>
#include <cstdint>

// ---------------- fixed problem shape ----------------
#define B_   64
#define D_   512
#define L0_  512
#define L1_  256
#define WS_  128
#define H0_  128
#define H1_  64
#define N0_  (L0_ + WS_)   // 640
#define N1_  (L1_ + WS_)   // 384
#define HT_  (H0_ + H1_)   // 192
// triangular pairs: scale0 T=5 -> 15 (ww = idx 14), scale1 T=3 -> 6 (ww = idx 5)
#define NP0_NW 14
#define NP1_NW 5
#define NCHUNK 4
#define BCH (B_ / NCHUNK)                       // 16 batches per chunk
#define JOBS_CH (BCH * (NP0_NW + NP1_NW))       // 304

// ---------------- device scratch ----------------
__device__ __nv_bfloat16 g_nx0[(size_t)B_ * L0_ * D_];
__device__ __nv_bfloat16 g_nx1[(size_t)B_ * L1_ * D_];
__device__ __nv_bfloat16 g_nw0[WS_ * D_];
__device__ __nv_bfloat16 g_nw1[WS_ * D_];
__device__ float g_selfx0[B_ * L0_];
__device__ float g_selfx1[B_ * L1_];
__device__ float g_selfw0[WS_];
__device__ float g_selfw1[WS_];
__device__ int   g_eidx0[N0_], g_eidx1[N1_];
__device__ int   g_memb0[N0_], g_memb1[N1_];
__device__ int   g_gstart0[H0_ + 1], g_gstart1[H1_ + 1];
__device__ int   g_cnt0[N0_], g_cnt1[N1_];
__device__ int   g_nvalid[2];
__device__ float g_posg[B_ * HT_];
#define GSUMTOT (B_ * (N0_ + N1_))   // 65536
__device__ float g_gsum[GSUMTOT];
__device__ float g_wwsum[2][WS_];    // batch-invariant word-word tile row sums
__device__ double g_loss[2];
__device__ int   g_redcnt;           // reduce completion ticket

// ---------------- adjacency: 4 nodes/block, both scales in one grid ----------------
// softmax row sums to 1 => at most one entry > 0.5 and it is the row max =>
// always inside top-k: adj_bin = (p > 0.5). No top-k machinery needed.
__global__ void __launch_bounds__(128)
adjq_kernel(const float* __restrict__ nod0, const float* __restrict__ hy0,
            const float* __restrict__ nod1, const float* __restrict__ hy1,
            float* __restrict__ adj0, float* __restrict__ adj1)
{
    const int blk = blockIdx.x;
    const int tid = threadIdx.x;

    const int S = (blk >= N0_ / 4);
    const int nbase = (S ? (blk - N0_ / 4) : blk) * 4;
    const int H = S ? H1_ : H0_;
    const float* enod = S ? nod1 : nod0;
    const float* ehy  = S ? hy1  : hy0;
    float* adj_out = S ? adj1 : adj0;
    int* eidx = S ? g_eidx1 : g_eidx0;

    __shared__ float xrow[4][D_];
    __shared__ float et[128][36];
    __shared__ float rbuf[128];
    __shared__ int   widx[4];

    #pragma unroll
    for (int r = 0; r < 4; r++)
        *(float4*)&xrow[r][tid * 4] = *(const float4*)(enod + (size_t)(nbase + r) * D_ + tid * 4);

    float acc[4] = {0.f, 0.f, 0.f, 0.f};
    const int nf4 = H * 8;
    for (int kk = 0; kk < D_; kk += 32) {
        __syncthreads();
        for (int f = tid; f < nf4; f += 128) {
            int h = f >> 3, c4 = f & 7;
            *(float4*)&et[h][c4 * 4] = *(const float4*)(ehy + (size_t)h * D_ + kk + c4 * 4);
        }
        __syncthreads();
        if (tid < H) {
            #pragma unroll
            for (int c4 = 0; c4 < 8; c4++) {
                float4 e4 = *(const float4*)&et[tid][c4 * 4];
                #pragma unroll
                for (int r = 0; r < 4; r++) {
                    float4 x4 = *(const float4*)&xrow[r][kk + c4 * 4];
                    acc[r] = fmaf(x4.x, e4.x, acc[r]);
                    acc[r] = fmaf(x4.y, e4.y, acc[r]);
                    acc[r] = fmaf(x4.z, e4.z, acc[r]);
                    acc[r] = fmaf(x4.w, e4.w, acc[r]);
                }
            }
        }
    }

    #pragma unroll
    for (int r = 0; r < 4; r++) {
        float z = (tid < H) ? fmaxf(3.0f * acc[r], 0.0f) : -1e30f;
        __syncthreads();
        rbuf[tid] = z; __syncthreads();
        for (int o = 64; o > 0; o >>= 1) { if (tid < o) rbuf[tid] = fmaxf(rbuf[tid], rbuf[tid + o]); __syncthreads(); }
        float zmax = rbuf[0]; __syncthreads();
        float e = (tid < H) ? __expf(z - zmax) : 0.f;
        rbuf[tid] = e; __syncthreads();
        for (int o = 64; o > 0; o >>= 1) { if (tid < o) rbuf[tid] += rbuf[tid + o]; __syncthreads(); }
        float ssum = rbuf[0];
        if (tid == 0) widx[r] = -1;
        __syncthreads();
        if (tid < H) {
            int bin = (e / ssum) > 0.5f;
            adj_out[(size_t)(nbase + r) * H + tid] = (float)bin;
            if (bin) widx[r] = tid;
        }
    }
    __syncthreads();
    if (tid < 4) eidx[nbase + tid] = widx[tid];
}

// ---------------- counts + group member lists ----------------
__global__ void __launch_bounds__(256)
cnt_kernel()
{
    const int S = blockIdx.x;
    const int N = S ? N1_ : N0_;
    const int H = S ? H1_ : H0_;
    const int* eidx = S ? g_eidx1 : g_eidx0;
    int* memb = S ? g_memb1 : g_memb0;
    int* gst  = S ? g_gstart1 : g_gstart0;
    int* cnt  = S ? g_cnt1 : g_cnt0;

    __shared__ int sz[128];
    __shared__ int scanb[128];
    __shared__ int cur[128];
    __shared__ int vc;
    const int tid = threadIdx.x;
    if (tid < H) sz[tid] = 0;
    if (tid == 0) vc = 0;
    __syncthreads();
    for (int n = tid; n < N; n += 256) {
        int e = eidx[n];
        if (e >= 0) atomicAdd(&sz[e], 1);
    }
    __syncthreads();
    if (tid < H) scanb[tid] = sz[tid];
    __syncthreads();
    for (int o = 1; o < H; o <<= 1) {
        int v = (tid < H && tid >= o) ? scanb[tid - o] : 0;
        __syncthreads();
        if (tid < H) scanb[tid] += v;
        __syncthreads();
    }
    if (tid < H) { gst[tid] = scanb[tid] - sz[tid]; cur[tid] = scanb[tid] - sz[tid]; }
    if (tid == 0) gst[H] = scanb[H - 1];
    __syncthreads();
    int local = 0;
    for (int n = tid; n < N; n += 256) {
        int e = eidx[n];
        int c = 0;
        if (e >= 0) {
            int p = atomicAdd(&cur[e], 1);
            memb[p] = n;
            c = sz[e] - 1;
        }
        cnt[n] = c;
        if (c > 0) local++;
    }
    atomicAdd(&vc, local);
    __syncthreads();
    if (tid == 0) g_nvalid[S] = vc;
}

// ---------------- normalize chunk -> bf16 + self-dot ----------------
// chunk covers x0 batches [c*16,(c+1)*16), x1 same; chunk 0 also words + init.
#define NORM_ROWS_X (BCH * L0_ + BCH * L1_)    // 12288
__global__ void __launch_bounds__(256)
normx_kernel(int chunk, const float* __restrict__ x0, const float* __restrict__ x1,
             const float* __restrict__ w0, const float* __restrict__ w1)
{
    if (chunk == 0 && blockIdx.x < GSUMTOT / 256) {
        int gid = blockIdx.x * 256 + threadIdx.x;
        g_gsum[gid] = 0.f;
        if (gid == 0) { g_loss[0] = 0.0; g_loss[1] = 0.0; g_redcnt = 0; }
    }

    const int gw   = (blockIdx.x * 256 + threadIdx.x) >> 5;
    const int lane = threadIdx.x & 31;
    const float* src;
    __nv_bfloat16* dst;
    float* selfp;
    int r = gw;
    if (r < BCH * L0_) {
        int row = chunk * BCH * L0_ + r;
        src = x0 + (size_t)row * D_; dst = g_nx0 + (size_t)row * D_; selfp = g_selfx0 + row;
    } else if ((r -= BCH * L0_) < BCH * L1_) {
        int row = chunk * BCH * L1_ + r;
        src = x1 + (size_t)row * D_; dst = g_nx1 + (size_t)row * D_; selfp = g_selfx1 + row;
    } else if ((r -= BCH * L1_) < WS_) {       // words only present in chunk-0 grid
        src = w0 + (size_t)r * D_; dst = g_nw0 + (size_t)r * D_; selfp = g_selfw0 + r;
    } else {
        r -= WS_;
        src = w1 + (size_t)r * D_; dst = g_nw1 + (size_t)r * D_; selfp = g_selfw1 + r;
    }

    float4 v[4];
    #pragma unroll
    for (int i = 0; i < 4; i++) v[i] = *(const float4*)(src + i * 128 + lane * 4);
    float ss = 0.f;
    #pragma unroll
    for (int i = 0; i < 4; i++) ss += v[i].x*v[i].x + v[i].y*v[i].y + v[i].z*v[i].z + v[i].w*v[i].w;
    #pragma unroll
    for (int o = 16; o > 0; o >>= 1) ss += __shfl_xor_sync(0xffffffffu, ss, o);
    float iv = 1.0f / fmaxf(sqrtf(ss), 1e-12f);
    float sd = 0.f;
    #pragma unroll
    for (int i = 0; i < 4; i++) {
        __nv_bfloat162 p0 = __floats2bfloat162_rn(v[i].x * iv, v[i].y * iv);
        __nv_bfloat162 p1 = __floats2bfloat162_rn(v[i].z * iv, v[i].w * iv);
        float2 f0 = __bfloat1622float2(p0);
        float2 f1 = __bfloat1622float2(p1);
        sd += f0.x*f0.x + f0.y*f0.y + f1.x*f1.x + f1.y*f1.y;
        uint2 pk; pk.x = *(uint32_t*)&p0; pk.y = *(uint32_t*)&p1;
        *(uint2*)(dst + i * 128 + lane * 4) = pk;
    }
    #pragma unroll
    for (int o = 16; o > 0; o >>= 1) sd += __shfl_xor_sync(0xffffffffu, sd, o);
    if (lane == 0) *selfp = sd;
}

// ---------------- per-(b,edge) positive group sums ----------------
// sum_{n!=m in group} s_nm = 10*(||sum of rows||^2 - sum selfdot); cnt within a
// group is sz-1 for all members, so loss needs only this total / (sz-1).
__global__ void __launch_bounds__(128)
posg_kernel()
{
    const int kg = blockIdx.x;
    const int S  = (kg >= H0_);
    const int k  = S ? kg - H0_ : kg;
    const int b  = blockIdx.y;
    const int tid = threadIdx.x;

    const int* gst  = S ? g_gstart1 : g_gstart0;
    const int* memb = S ? g_memb1 : g_memb0;
    const int L = S ? L1_ : L0_;
    const __nv_bfloat16* nx = S ? g_nx1 : g_nx0;
    const __nv_bfloat16* nw = S ? g_nw1 : g_nw0;
    const float* selfx = S ? g_selfx1 : g_selfx0;
    const float* selfw = S ? g_selfw1 : g_selfw0;

    const int s0 = gst[k], s1 = gst[k + 1];
    const int szk = s1 - s0;
    float* outp = &g_posg[b * HT_ + kg];
    if (szk < 2) { if (tid == 0) *outp = 0.f; return; }

    float g0 = 0.f, g1 = 0.f, g2 = 0.f, g3 = 0.f;
    float selfs = 0.f;
    for (int i = s0; i < s1; i++) {
        int n = memb[i];
        const __nv_bfloat16* row = (n < L) ? nx + ((size_t)b * L + n) * D_
                                           : nw + (size_t)(n - L) * D_;
        uint2 u = *(const uint2*)(row + tid * 4);
        __nv_bfloat162 p0 = *(__nv_bfloat162*)&u.x;
        __nv_bfloat162 p1 = *(__nv_bfloat162*)&u.y;
        float2 f0 = __bfloat1622float2(p0);
        float2 f1 = __bfloat1622float2(p1);
        g0 += f0.x; g1 += f0.y; g2 += f1.x; g3 += f1.y;
    }
    for (int i = s0 + tid; i < s1; i += 128) {
        int n = memb[i];
        selfs += (n < L) ? selfx[(size_t)b * L + n] : selfw[n - L];
    }
    float val = g0*g0 + g1*g1 + g2*g2 + g3*g3;
    #pragma unroll
    for (int o = 16; o > 0; o >>= 1) {
        val   += __shfl_xor_sync(0xffffffffu, val, o);
        selfs += __shfl_xor_sync(0xffffffffu, selfs, o);
    }
    __shared__ float sv[4], sf[4];
    if ((tid & 31) == 0) { sv[tid >> 5] = val; sf[tid >> 5] = selfs; }
    __syncthreads();
    if (tid == 0) {
        float gv = sv[0] + sv[1] + sv[2] + sv[3];
        float sc = sf[0] + sf[1] + sf[2] + sf[3];
        *outp = 10.0f * (gv - sc) / (float)(szk - 1);
    }
}

// ---------------- fused sim GEMM (bf16 mma + ldmatrix, 4-stage pipeline) ----------------
#define BM 128
#define BN 128
#define BK 32
#define SKEW 8
#define SROW ((BK + SKEW) * 2)      // 80 bytes per smem row
#define TILEB (BM * SROW)           // 10240 bytes per tile buffer
#define NKT (D_ / BK)               // 16
#define NSTAGE 4
#define SIM_DSMEM (2 * NSTAGE * TILEB)   // 81920

__device__ __forceinline__ uint32_t smem_u32(const void* p) {
    uint32_t a;
    asm("{ .reg .u64 t; cvta.to.shared.u64 t, %1; cvt.u32.u64 %0, t; }" : "=r"(a) : "l"(p));
    return a;
}
__device__ __forceinline__ void cp_async16(uint32_t saddr, const void* gptr) {
    asm volatile("cp.async.cg.shared.global [%0], [%1], 16;\n" :: "r"(saddr), "l"(gptr));
}
__device__ __forceinline__ void cp_commit() { asm volatile("cp.async.commit_group;\n"); }
template<int NN> __device__ __forceinline__ void cp_wait() {
    asm volatile("cp.async.wait_group %0;\n" :: "n"(NN));
}
__device__ __forceinline__ void ldsm_x4(uint32_t r[4], uint32_t saddr) {
    asm volatile("ldmatrix.sync.aligned.m8n8.x4.shared.b16 {%0,%1,%2,%3}, [%4];"
        : "=r"(r[0]), "=r"(r[1]), "=r"(r[2]), "=r"(r[3]) : "r"(saddr));
}
__device__ __forceinline__ void mma_bf16(float c[4],
    uint32_t a0, uint32_t a1, uint32_t a2, uint32_t a3, uint32_t b0, uint32_t b1)
{
    asm volatile("mma.sync.aligned.m16n8k16.row.col.f32.bf16.bf16.f32 "
        "{%0,%1,%2,%3}, {%4,%5,%6,%7}, {%8,%9}, {%0,%1,%2,%3};\n"
        : "+f"(c[0]), "+f"(c[1]), "+f"(c[2]), "+f"(c[3])
        : "r"(a0), "r"(a1), "r"(a2), "r"(a3), "r"(b0), "r"(b1));
}

// one launch per batch-chunk. jobs: 16 batches x (14 + 5) pairs = 304; chunk 0
// appends the 2 batch-invariant ww tiles.
__global__ void __launch_bounds__(256, 2)
sim_kernel(int bbase)
{
    extern __shared__ char dsm[];
    __shared__ float rsmem[BM], csmem[BN];

    const int tid  = threadIdx.x;
    const int lane = tid & 31;
    const int warp = tid >> 5;
    const int warpM = warp >> 1;
    const int warpN = warp & 1;

    // decode packed job id within chunk
    int gid = blockIdx.x;
    int S, p, b;
    if (gid < BCH * NP0_NW)                        { S = 0; b = bbase + gid / NP0_NW; p = gid % NP0_NW; }
    else if ((gid -= BCH * NP0_NW) < BCH * NP1_NW) { S = 1; b = bbase + gid / NP1_NW; p = gid % NP1_NW; }
    else if (gid == BCH * NP1_NW)                  { S = 0; b = 0; p = 14; }   // ww (chunk 0 only)
    else                                           { S = 1; b = 0; p = 5;  }

    const int T = S ? (N1_ >> 7) : (N0_ >> 7);
    int rt = 0;
    while (p >= T - rt) { p -= T - rt; rt++; }
    const int ct = rt + p;
    const bool diag = (rt == ct);

    const int rb = rt * BM, cb = ct * BN;
    const int L = S ? L1_ : L0_;
    const int N = S ? N1_ : N0_;
    const bool ww = diag && (rb >= L);

    const __nv_bfloat16* nx = S ? g_nx1 : g_nx0;
    const __nv_bfloat16* nw = S ? g_nw1 : g_nw0;
    float* gsum = g_gsum + (S ? B_ * N0_ : 0) + (size_t)b * N;

    const __nv_bfloat16* baseA = (rb < L) ? nx + ((size_t)b * L + rb) * D_
                                          : nw + (size_t)(rb - L) * D_;
    const __nv_bfloat16* baseB = (cb < L) ? nx + ((size_t)b * L + cb) * D_
                                          : nw + (size_t)(cb - L) * D_;

    if (tid < BM) { rsmem[tid] = 0.f; csmem[tid] = 0.f; }

    // cp.async slots: 2 x 16B per tile per thread
    const int r0 = tid >> 2, seg0 = tid & 3;
    const int r1 = (tid + 256) >> 2, seg1 = (tid + 256) & 3;
    const uint32_t asb = smem_u32(dsm);                       // A stages 0..3
    const uint32_t bsb = asb + NSTAGE * TILEB;                // B stages 0..3
    const uint32_t sA0 = asb + r0 * SROW + seg0 * 16;
    const uint32_t sA1 = asb + r1 * SROW + seg1 * 16;
    const uint32_t sB0 = bsb + r0 * SROW + seg0 * 16;
    const uint32_t sB1 = bsb + r1 * SROW + seg1 * 16;

    // ldmatrix base addresses (stage offset added in loop)
    uint32_t aAddr[2], bAddr[4];
    {
        const int arow = (lane & 15), ach = (lane >> 4) * 8;
        #pragma unroll
        for (int mi = 0; mi < 2; mi++)
            aAddr[mi] = asb + (warpM * 32 + mi * 16 + arow) * SROW + ach * 2;
        const int bn = (lane & 7) + ((lane >> 4) & 1) * 8;
        const int bkh = ((lane >> 3) & 1) * 8;
        #pragma unroll
        for (int pr = 0; pr < 4; pr++)
            bAddr[pr] = bsb + (warpN * 64 + pr * 16 + bn) * SROW + bkh * 2;
    }

    float acc[2][8][4];
    #pragma unroll
    for (int mi = 0; mi < 2; mi++)
        #pragma unroll
        for (int ni = 0; ni < 8; ni++)
            #pragma unroll
            for (int r = 0; r < 4; r++) acc[mi][ni][r] = 0.f;

    auto load_stage = [&](int st, int kt) {
        const uint32_t so = (uint32_t)st * TILEB;
        const int kb = kt * BK;
        cp_async16(sA0 + so, baseA + (size_t)r0 * D_ + kb + seg0 * 8);
        cp_async16(sB0 + so, baseB + (size_t)r0 * D_ + kb + seg0 * 8);
        cp_async16(sA1 + so, baseA + (size_t)r1 * D_ + kb + seg1 * 8);
        cp_async16(sB1 + so, baseB + (size_t)r1 * D_ + kb + seg1 * 8);
        cp_commit();
    };

    load_stage(0, 0);
    load_stage(1, 1);
    load_stage(2, 2);

    int st = 0;
    #pragma unroll 1
    for (int kt = 0; kt < NKT; ++kt) {
        if (kt < NKT - 2)       cp_wait<2>();
        else if (kt == NKT - 2) cp_wait<1>();
        else                    cp_wait<0>();
        __syncthreads();   // stage st visible; stage (st+3)%4 fully drained by all warps
        if (kt + 3 < NKT) {
            int nst = st + 3; if (nst >= NSTAGE) nst -= NSTAGE;
            load_stage(nst, kt + 3);
        }

        const uint32_t bofs = (uint32_t)st * TILEB;
        #pragma unroll
        for (int kk = 0; kk < BK; kk += 16) {
            uint32_t af[2][4];
            ldsm_x4(af[0], aAddr[0] + bofs + kk * 2);
            ldsm_x4(af[1], aAddr[1] + bofs + kk * 2);
            #pragma unroll
            for (int pr = 0; pr < 4; pr++) {
                uint32_t bf[4];
                ldsm_x4(bf, bAddr[pr] + bofs + kk * 2);
                mma_bf16(acc[0][pr * 2    ], af[0][0], af[0][1], af[0][2], af[0][3], bf[0], bf[1]);
                mma_bf16(acc[1][pr * 2    ], af[1][0], af[1][1], af[1][2], af[1][3], bf[0], bf[1]);
                mma_bf16(acc[0][pr * 2 + 1], af[0][0], af[0][1], af[0][2], af[0][3], bf[2], bf[3]);
                mma_bf16(acc[1][pr * 2 + 1], af[1][0], af[1][1], af[1][2], af[1][3], bf[2], bf[3]);
            }
        }
        if (++st >= NSTAGE) st = 0;
    }

    // ---- epilogue: e = 4096*exp(s-10) = 2^(a*C2 + CS) via ex2.approx.f16x2 ----
    const float C2 = 14.4269504089f;    // 10*log2(e)
    const float CS = -2.4269504089f;    // -C2 + 12 (x2^12 keeps f16 normal)
    const int qrow = lane >> 2;
    float colS[8][2];
    #pragma unroll
    for (int ni = 0; ni < 8; ni++) { colS[ni][0] = 0.f; colS[ni][1] = 0.f; }

    #pragma unroll
    for (int mi = 0; mi < 2; mi++) {
        #pragma unroll
        for (int h = 0; h < 2; h++) {
            const int lrow = warpM * 32 + mi * 16 + h * 8 + qrow;
            float rs = 0.f;
            #pragma unroll
            for (int ni = 0; ni < 8; ni++) {
                float x0 = fmaf(acc[mi][ni][h * 2 + 0], C2, CS);
                float x1 = fmaf(acc[mi][ni][h * 2 + 1], C2, CS);
                __half2 he = h2exp2(__floats2half2_rn(x0, x1));
                float2 ef = __half22float2(he);
                if (diag) {
                    const int lcol0 = warpN * 64 + ni * 8 + (lane & 3) * 2;
                    if (lcol0     == lrow) ef.x = 4096.0f;   // exact diagonal exp(0)*2^12
                    if (lcol0 + 1 == lrow) ef.y = 4096.0f;
                } else {
                    colS[ni][0] += ef.x;
                    colS[ni][1] += ef.y;
                }
                rs += ef.x + ef.y;
            }
            rs += __shfl_xor_sync(0xffffffffu, rs, 1);
            rs += __shfl_xor_sync(0xffffffffu, rs, 2);
            if ((lane & 3) == 0) atomicAdd(&rsmem[lrow], rs);
        }
    }
    if (!diag) {
        #pragma unroll
        for (int ni = 0; ni < 8; ni++) {
            #pragma unroll
            for (int c = 0; c < 2; c++) {
                float v = colS[ni][c];
                v += __shfl_xor_sync(0xffffffffu, v, 4);
                v += __shfl_xor_sync(0xffffffffu, v, 8);
                v += __shfl_xor_sync(0xffffffffu, v, 16);
                if (qrow == 0) {
                    const int lcol = warpN * 64 + ni * 8 + (lane & 3) * 2 + c;
                    atomicAdd(&csmem[lcol], v);
                }
            }
        }
    }

    __syncthreads();
    if (tid < BM) {
        if (ww) {
            g_wwsum[S][tid] = rsmem[tid];       // written once (chunk-0 ww job)
        } else {
            atomicAdd(gsum + rb + tid, rsmem[tid]);
            if (!diag) atomicAdd(gsum + cb + tid, csmem[tid]);
        }
    }
}

// ---------------- per-(b,scale) loss reduction + fused finalize (ticket) ----------------
__global__ void __launch_bounds__(256)
reduce_kernel(float* out_loss)
{
    const int b = blockIdx.x, S = blockIdx.y, tid = threadIdx.x;
    const int N = S ? N1_ : N0_;
    const int H = S ? H1_ : H0_;
    const int L = S ? L1_ : L0_;
    const float* gsum = g_gsum + (S ? B_ * N0_ : 0) + (size_t)b * N;
    const int* cnt = S ? g_cnt1 : g_cnt0;
    const float* posg = g_posg + b * HT_ + (S ? H0_ : 0);

    const float LOGSC = 8.3177661667f;   // ln(4096)
    float local = 0.f;
    for (int n = tid; n < N; n += 256) {
        if (cnt[n] > 0) {
            float rs = gsum[n];
            if (n >= L) rs += g_wwsum[S][n - L];    // batch-invariant word-word part
            local += 10.0f + __logf(rs) - LOGSC;
        }
    }
    for (int k = tid; k < H; k += 256) local -= posg[k];

    #pragma unroll
    for (int o = 16; o > 0; o >>= 1) local += __shfl_down_sync(0xffffffffu, local, o);
    __shared__ float sp[8];
    if ((tid & 31) == 0) sp[tid >> 5] = local;
    __syncthreads();
    if (tid == 0) {
        float t = 0.f;
        #pragma unroll
        for (int i = 0; i < 8; i++) t += sp[i];
        atomicAdd(&g_loss[S], (double)t);
        __threadfence();
        int done = atomicAdd(&g_redcnt, 1);
        if (done == 2 * B_ - 1) {               // last of 128 blocks: finalize
            double l = 0.0;
            #pragma unroll
            for (int s = 0; s < 2; s++) {
                int nv = g_nvalid[s];
                if (nv > 0) l += g_loss[s] / (double)(B_ * nv);
            }
            *out_loss = (float)l;
        }
    }
}

// ---------------- launch: chunked normx/sim pipeline across streams ----------------
extern "C" void kernel_launch(void* const* d_in, const int* in_sizes, int n_in,
                              void* d_out, int out_size)
{
    const float* x0   = (const float*)d_in[0];
    const float* x1   = (const float*)d_in[1];
    const float* w0   = (const float*)d_in[2];
    const float* w1   = (const float*)d_in[3];
    const float* hy0  = (const float*)d_in[4];
    const float* hy1  = (const float*)d_in[5];
    const float* nod0 = (const float*)d_in[6];
    const float* nod1 = (const float*)d_in[7];
    float* out = (float*)d_out;

    float* adj0  = out;
    float* adj1  = out + (size_t)N0_ * H0_;
    float* lossp = out + (size_t)N0_ * H0_ + (size_t)N1_ * H1_;

    static cudaStream_t s1 = nullptr, s2 = nullptr, s3 = nullptr;
    static cudaEvent_t ev0, evC[NCHUNK], evP, evS2, evS3;
    if (s1 == nullptr) {
        int loPri = 0, hiPri = 0;
        cudaDeviceGetStreamPriorityRange(&loPri, &hiPri);
        cudaStreamCreateWithPriority(&s1, cudaStreamNonBlocking, loPri);
        cudaStreamCreateWithFlags(&s2, cudaStreamNonBlocking);
        cudaStreamCreateWithFlags(&s3, cudaStreamNonBlocking);
        cudaEventCreateWithFlags(&ev0, cudaEventDisableTiming);
        for (int c = 0; c < NCHUNK; c++) cudaEventCreateWithFlags(&evC[c], cudaEventDisableTiming);
        cudaEventCreateWithFlags(&evP, cudaEventDisableTiming);
        cudaEventCreateWithFlags(&evS2, cudaEventDisableTiming);
        cudaEventCreateWithFlags(&evS3, cudaEventDisableTiming);
        cudaFuncSetAttribute(sim_kernel, cudaFuncAttributeMaxDynamicSharedMemorySize, SIM_DSMEM);
    }

    // fork: low-priority side stream runs adjacency chain
    cudaEventRecord(ev0, 0);
    cudaStreamWaitEvent(s1, ev0, 0);
    cudaStreamWaitEvent(s2, ev0, 0);
    cudaStreamWaitEvent(s3, ev0, 0);

    adjq_kernel<<<N0_ / 4 + N1_ / 4, 128, 0, s1>>>(nod0, hy0, nod1, hy1, adj0, adj1);
    cnt_kernel<<<2, 256, 0, s1>>>();

    // normx chunks on main stream; sim chunks alternate on s2/s3
    for (int c = 0; c < NCHUNK; c++) {
        const int rows = NORM_ROWS_X + (c == 0 ? 2 * WS_ : 0);
        normx_kernel<<<rows / 8, 256>>>(c, x0, x1, w0, w1);
        cudaEventRecord(evC[c], 0);
        cudaStream_t ss = (c & 1) ? s3 : s2;
        cudaStreamWaitEvent(ss, evC[c], 0);
        const int jobs = JOBS_CH + (c == 0 ? 2 : 0);
        sim_kernel<<<jobs, 256, SIM_DSMEM, ss>>>(c * BCH);
    }
    cudaEventRecord(evS2, s2);
    cudaEventRecord(evS3, s3);

    // posg needs all rows (evC[3]) + cnt (s1 order); backfills under sim
    cudaStreamWaitEvent(s1, evC[NCHUNK - 1], 0);
    posg_kernel<<<dim3(HT_, B_), 128, 0, s1>>>();
    cudaEventRecord(evP, s1);

    // join: reduce(+finalize) needs all sim chunks + posg
    cudaStreamWaitEvent(0, evS2, 0);
    cudaStreamWaitEvent(0, evS3, 0);
    cudaStreamWaitEvent(0, evP, 0);
    reduce_kernel<<<dim3(B_, 2), 256>>>(lossp);
}

// round 16
// speedup vs baseline: 1.1396x; 1.1396x over previous
#include <cuda_runtime.h>
#include <cuda_bf16.h>
#include <cuda_fp16.h>
#include <cstdint>

// ---------------- fixed problem shape ----------------
#define B_   64
#define D_   512
#define L0_  512
#define L1_  256
#define WS_  128
#define H0_  128
#define H1_  64
#define N0_  (L0_ + WS_)   // 640
#define N1_  (L1_ + WS_)   // 384
#define HT_  (H0_ + H1_)   // 192
// triangular pairs: scale0 T=5 -> 15 (ww = idx 14), scale1 T=3 -> 6 (ww = idx 5)
#define NP0_NW 14
#define NP1_NW 5
#define SIM_JOBS (NP0_NW * B_ + NP1_NW * B_ + 2)   // 896 + 320 + 2 = 1218

// ---------------- device scratch ----------------
__device__ __nv_bfloat16 g_nx0[(size_t)B_ * L0_ * D_];
__device__ __nv_bfloat16 g_nx1[(size_t)B_ * L1_ * D_];
__device__ __nv_bfloat16 g_nw0[WS_ * D_];
__device__ __nv_bfloat16 g_nw1[WS_ * D_];
__device__ float g_selfx0[B_ * L0_];
__device__ float g_selfx1[B_ * L1_];
__device__ float g_selfw0[WS_];
__device__ float g_selfw1[WS_];
__device__ int   g_eidx0[N0_], g_eidx1[N1_];
__device__ int   g_memb0[N0_], g_memb1[N1_];
__device__ int   g_gstart0[H0_ + 1], g_gstart1[H1_ + 1];
__device__ int   g_cnt0[N0_], g_cnt1[N1_];
__device__ int   g_nvalid[2];
__device__ float g_posg[B_ * HT_];
#define GSUMTOT (B_ * (N0_ + N1_))   // 65536
__device__ float g_gsum[GSUMTOT];
__device__ float g_wwsum[2][WS_];    // batch-invariant word-word tile row sums
__device__ double g_loss[2];
__device__ int   g_redcnt;           // reduce completion ticket

// ---------------- adjacency: 4 nodes/block, both scales in one grid ----------------
// softmax row sums to 1 => at most one entry > 0.5 and it is the row max =>
// always inside top-k: adj_bin = (p > 0.5). No top-k machinery needed.
__global__ void __launch_bounds__(128)
adjq_kernel(const float* __restrict__ nod0, const float* __restrict__ hy0,
            const float* __restrict__ nod1, const float* __restrict__ hy1,
            float* __restrict__ adj0, float* __restrict__ adj1)
{
    const int blk = blockIdx.x;
    const int tid = threadIdx.x;

    const int S = (blk >= N0_ / 4);
    const int nbase = (S ? (blk - N0_ / 4) : blk) * 4;
    const int H = S ? H1_ : H0_;
    const float* enod = S ? nod1 : nod0;
    const float* ehy  = S ? hy1  : hy0;
    float* adj_out = S ? adj1 : adj0;
    int* eidx = S ? g_eidx1 : g_eidx0;

    __shared__ float xrow[4][D_];
    __shared__ float et[128][36];
    __shared__ float rbuf[128];
    __shared__ int   widx[4];

    #pragma unroll
    for (int r = 0; r < 4; r++)
        *(float4*)&xrow[r][tid * 4] = *(const float4*)(enod + (size_t)(nbase + r) * D_ + tid * 4);

    float acc[4] = {0.f, 0.f, 0.f, 0.f};
    const int nf4 = H * 8;
    for (int kk = 0; kk < D_; kk += 32) {
        __syncthreads();
        for (int f = tid; f < nf4; f += 128) {
            int h = f >> 3, c4 = f & 7;
            *(float4*)&et[h][c4 * 4] = *(const float4*)(ehy + (size_t)h * D_ + kk + c4 * 4);
        }
        __syncthreads();
        if (tid < H) {
            #pragma unroll
            for (int c4 = 0; c4 < 8; c4++) {
                float4 e4 = *(const float4*)&et[tid][c4 * 4];
                #pragma unroll
                for (int r = 0; r < 4; r++) {
                    float4 x4 = *(const float4*)&xrow[r][kk + c4 * 4];
                    acc[r] = fmaf(x4.x, e4.x, acc[r]);
                    acc[r] = fmaf(x4.y, e4.y, acc[r]);
                    acc[r] = fmaf(x4.z, e4.z, acc[r]);
                    acc[r] = fmaf(x4.w, e4.w, acc[r]);
                }
            }
        }
    }

    #pragma unroll
    for (int r = 0; r < 4; r++) {
        float z = (tid < H) ? fmaxf(3.0f * acc[r], 0.0f) : -1e30f;
        __syncthreads();
        rbuf[tid] = z; __syncthreads();
        for (int o = 64; o > 0; o >>= 1) { if (tid < o) rbuf[tid] = fmaxf(rbuf[tid], rbuf[tid + o]); __syncthreads(); }
        float zmax = rbuf[0]; __syncthreads();
        float e = (tid < H) ? __expf(z - zmax) : 0.f;
        rbuf[tid] = e; __syncthreads();
        for (int o = 64; o > 0; o >>= 1) { if (tid < o) rbuf[tid] += rbuf[tid + o]; __syncthreads(); }
        float ssum = rbuf[0];
        if (tid == 0) widx[r] = -1;
        __syncthreads();
        if (tid < H) {
            int bin = (e / ssum) > 0.5f;
            adj_out[(size_t)(nbase + r) * H + tid] = (float)bin;
            if (bin) widx[r] = tid;
        }
    }
    __syncthreads();
    if (tid < 4) eidx[nbase + tid] = widx[tid];
}

// ---------------- counts + group member lists ----------------
__global__ void __launch_bounds__(256)
cnt_kernel()
{
    const int S = blockIdx.x;
    const int N = S ? N1_ : N0_;
    const int H = S ? H1_ : H0_;
    const int* eidx = S ? g_eidx1 : g_eidx0;
    int* memb = S ? g_memb1 : g_memb0;
    int* gst  = S ? g_gstart1 : g_gstart0;
    int* cnt  = S ? g_cnt1 : g_cnt0;

    __shared__ int sz[128];
    __shared__ int scanb[128];
    __shared__ int cur[128];
    __shared__ int vc;
    const int tid = threadIdx.x;
    if (tid < H) sz[tid] = 0;
    if (tid == 0) vc = 0;
    __syncthreads();
    for (int n = tid; n < N; n += 256) {
        int e = eidx[n];
        if (e >= 0) atomicAdd(&sz[e], 1);
    }
    __syncthreads();
    if (tid < H) scanb[tid] = sz[tid];
    __syncthreads();
    for (int o = 1; o < H; o <<= 1) {
        int v = (tid < H && tid >= o) ? scanb[tid - o] : 0;
        __syncthreads();
        if (tid < H) scanb[tid] += v;
        __syncthreads();
    }
    if (tid < H) { gst[tid] = scanb[tid] - sz[tid]; cur[tid] = scanb[tid] - sz[tid]; }
    if (tid == 0) gst[H] = scanb[H - 1];
    __syncthreads();
    int local = 0;
    for (int n = tid; n < N; n += 256) {
        int e = eidx[n];
        int c = 0;
        if (e >= 0) {
            int p = atomicAdd(&cur[e], 1);
            memb[p] = n;
            c = sz[e] - 1;
        }
        cnt[n] = c;
        if (c > 0) local++;
    }
    atomicAdd(&vc, local);
    __syncthreads();
    if (tid == 0) g_nvalid[S] = vc;
}

// ---------------- normalize -> bf16 + self-dot (+ fused accumulator init) ----------------
__global__ void __launch_bounds__(256)
normx_kernel(const float* __restrict__ x0, const float* __restrict__ x1,
             const float* __restrict__ w0, const float* __restrict__ w1)
{
    // fused init: zero g_gsum / g_loss / ticket (graph replays re-run every launch)
    if (blockIdx.x < GSUMTOT / 256) {
        int gid = blockIdx.x * 256 + threadIdx.x;
        g_gsum[gid] = 0.f;
        if (gid == 0) { g_loss[0] = 0.0; g_loss[1] = 0.0; g_redcnt = 0; }
    }

    const int gw   = (blockIdx.x * 256 + threadIdx.x) >> 5;
    const int lane = threadIdx.x & 31;
    const float* src;
    __nv_bfloat16* dst;
    float* selfp;
    int r = gw;
    if (r < B_ * L0_)                    { src = x0 + (size_t)r * D_; dst = g_nx0 + (size_t)r * D_; selfp = g_selfx0 + r; }
    else if ((r -= B_ * L0_) < B_ * L1_) { src = x1 + (size_t)r * D_; dst = g_nx1 + (size_t)r * D_; selfp = g_selfx1 + r; }
    else if ((r -= B_ * L1_) < WS_)      { src = w0 + (size_t)r * D_; dst = g_nw0 + (size_t)r * D_; selfp = g_selfw0 + r; }
    else { r -= WS_;                       src = w1 + (size_t)r * D_; dst = g_nw1 + (size_t)r * D_; selfp = g_selfw1 + r; }

    float4 v[4];
    #pragma unroll
    for (int i = 0; i < 4; i++) v[i] = *(const float4*)(src + i * 128 + lane * 4);
    float ss = 0.f;
    #pragma unroll
    for (int i = 0; i < 4; i++) ss += v[i].x*v[i].x + v[i].y*v[i].y + v[i].z*v[i].z + v[i].w*v[i].w;
    #pragma unroll
    for (int o = 16; o > 0; o >>= 1) ss += __shfl_xor_sync(0xffffffffu, ss, o);
    float iv = 1.0f / fmaxf(sqrtf(ss), 1e-12f);
    float sd = 0.f;
    #pragma unroll
    for (int i = 0; i < 4; i++) {
        __nv_bfloat162 p0 = __floats2bfloat162_rn(v[i].x * iv, v[i].y * iv);
        __nv_bfloat162 p1 = __floats2bfloat162_rn(v[i].z * iv, v[i].w * iv);
        float2 f0 = __bfloat1622float2(p0);
        float2 f1 = __bfloat1622float2(p1);
        sd += f0.x*f0.x + f0.y*f0.y + f1.x*f1.x + f1.y*f1.y;
        uint2 pk; pk.x = *(uint32_t*)&p0; pk.y = *(uint32_t*)&p1;
        *(uint2*)(dst + i * 128 + lane * 4) = pk;
    }
    #pragma unroll
    for (int o = 16; o > 0; o >>= 1) sd += __shfl_xor_sync(0xffffffffu, sd, o);
    if (lane == 0) *selfp = sd;
}

// ---------------- per-(b,edge) positive group sums ----------------
// sum_{n!=m in group} s_nm = 10*(||sum of rows||^2 - sum selfdot); cnt within a
// group is sz-1 for all members, so loss needs only this total / (sz-1).
__global__ void __launch_bounds__(128)
posg_kernel()
{
    const int kg = blockIdx.x;
    const int S  = (kg >= H0_);
    const int k  = S ? kg - H0_ : kg;
    const int b  = blockIdx.y;
    const int tid = threadIdx.x;

    const int* gst  = S ? g_gstart1 : g_gstart0;
    const int* memb = S ? g_memb1 : g_memb0;
    const int L = S ? L1_ : L0_;
    const __nv_bfloat16* nx = S ? g_nx1 : g_nx0;
    const __nv_bfloat16* nw = S ? g_nw1 : g_nw0;
    const float* selfx = S ? g_selfx1 : g_selfx0;
    const float* selfw = S ? g_selfw1 : g_selfw0;

    const int s0 = gst[k], s1 = gst[k + 1];
    const int szk = s1 - s0;
    float* outp = &g_posg[b * HT_ + kg];
    if (szk < 2) { if (tid == 0) *outp = 0.f; return; }

    float g0 = 0.f, g1 = 0.f, g2 = 0.f, g3 = 0.f;
    float selfs = 0.f;
    for (int i = s0; i < s1; i++) {
        int n = memb[i];
        const __nv_bfloat16* row = (n < L) ? nx + ((size_t)b * L + n) * D_
                                           : nw + (size_t)(n - L) * D_;
        uint2 u = *(const uint2*)(row + tid * 4);
        __nv_bfloat162 p0 = *(__nv_bfloat162*)&u.x;
        __nv_bfloat162 p1 = *(__nv_bfloat162*)&u.y;
        float2 f0 = __bfloat1622float2(p0);
        float2 f1 = __bfloat1622float2(p1);
        g0 += f0.x; g1 += f0.y; g2 += f1.x; g3 += f1.y;
    }
    for (int i = s0 + tid; i < s1; i += 128) {
        int n = memb[i];
        selfs += (n < L) ? selfx[(size_t)b * L + n] : selfw[n - L];
    }
    float val = g0*g0 + g1*g1 + g2*g2 + g3*g3;
    #pragma unroll
    for (int o = 16; o > 0; o >>= 1) {
        val   += __shfl_xor_sync(0xffffffffu, val, o);
        selfs += __shfl_xor_sync(0xffffffffu, selfs, o);
    }
    __shared__ float sv[4], sf[4];
    if ((tid & 31) == 0) { sv[tid >> 5] = val; sf[tid >> 5] = selfs; }
    __syncthreads();
    if (tid == 0) {
        float gv = sv[0] + sv[1] + sv[2] + sv[3];
        float sc = sf[0] + sf[1] + sf[2] + sf[3];
        *outp = 10.0f * (gv - sc) / (float)(szk - 1);
    }
}

// ---------------- fused sim GEMM (bf16 mma + ldmatrix, BK=64, double buffer) ----------------
#define BM 128
#define BN 128
#define BK 64
#define SKEW 8
#define SROW ((BK + SKEW) * 2)      // 144 bytes per smem row
#define TILEB (BM * SROW)           // 18432 bytes per tile buffer
#define NKT (D_ / BK)               // 8
#define NSTAGE 2
#define SIM_DSMEM (2 * NSTAGE * TILEB)   // 73728

__device__ __forceinline__ uint32_t smem_u32(const void* p) {
    uint32_t a;
    asm("{ .reg .u64 t; cvta.to.shared.u64 t, %1; cvt.u32.u64 %0, t; }" : "=r"(a) : "l"(p));
    return a;
}
__device__ __forceinline__ void cp_async16(uint32_t saddr, const void* gptr) {
    asm volatile("cp.async.cg.shared.global [%0], [%1], 16;\n" :: "r"(saddr), "l"(gptr));
}
__device__ __forceinline__ void cp_commit() { asm volatile("cp.async.commit_group;\n"); }
template<int NN> __device__ __forceinline__ void cp_wait() {
    asm volatile("cp.async.wait_group %0;\n" :: "n"(NN));
}
__device__ __forceinline__ void ldsm_x4(uint32_t r[4], uint32_t saddr) {
    asm volatile("ldmatrix.sync.aligned.m8n8.x4.shared.b16 {%0,%1,%2,%3}, [%4];"
        : "=r"(r[0]), "=r"(r[1]), "=r"(r[2]), "=r"(r[3]) : "r"(saddr));
}
__device__ __forceinline__ void mma_bf16(float c[4],
    uint32_t a0, uint32_t a1, uint32_t a2, uint32_t a3, uint32_t b0, uint32_t b1)
{
    asm volatile("mma.sync.aligned.m16n8k16.row.col.f32.bf16.bf16.f32 "
        "{%0,%1,%2,%3}, {%4,%5,%6,%7}, {%8,%9}, {%0,%1,%2,%3};\n"
        : "+f"(c[0]), "+f"(c[1]), "+f"(c[2]), "+f"(c[3])
        : "r"(a0), "r"(a1), "r"(a2), "r"(a3), "r"(b0), "r"(b1));
}

// Flat 1-D grid of exactly SIM_JOBS useful CTAs (no early-exit holes):
//   [0, 896)        scale0 non-ww: b = g/14, p = g%14   (ww pair is triangular idx 14)
//   [896, 1216)     scale1 non-ww: b = g/5,  p = g%5    (ww pair is triangular idx 5)
//   1216            scale0 ww (p=14, b=0)
//   1217            scale1 ww (p=5,  b=0)
__global__ void __launch_bounds__(256, 2)
sim_kernel()
{
    extern __shared__ char dsm[];
    __shared__ float rsmem[BM], csmem[BN];

    const int tid  = threadIdx.x;
    const int lane = tid & 31;
    const int warp = tid >> 5;
    const int warpM = warp >> 1;
    const int warpN = warp & 1;

    // decode packed job id
    int gid = blockIdx.x;
    int S, p, b;
    if (gid < NP0_NW * B_)            { S = 0; b = gid / NP0_NW; p = gid % NP0_NW; }
    else if ((gid -= NP0_NW * B_) < NP1_NW * B_) { S = 1; b = gid / NP1_NW; p = gid % NP1_NW; }
    else if (gid == NP1_NW * B_)      { S = 0; b = 0; p = 14; }
    else                              { S = 1; b = 0; p = 5; }

    const int T = S ? (N1_ >> 7) : (N0_ >> 7);
    int rt = 0;
    while (p >= T - rt) { p -= T - rt; rt++; }
    const int ct = rt + p;
    const bool diag = (rt == ct);

    const int rb = rt * BM, cb = ct * BN;
    const int L = S ? L1_ : L0_;
    const int N = S ? N1_ : N0_;
    const bool ww = diag && (rb >= L);       // word-word tile: batch-invariant (b==0 only in grid)

    const __nv_bfloat16* nx = S ? g_nx1 : g_nx0;
    const __nv_bfloat16* nw = S ? g_nw1 : g_nw0;
    float* gsum = g_gsum + (S ? B_ * N0_ : 0) + (size_t)b * N;

    const __nv_bfloat16* baseA = (rb < L) ? nx + ((size_t)b * L + rb) * D_
                                          : nw + (size_t)(rb - L) * D_;
    const __nv_bfloat16* baseB = (cb < L) ? nx + ((size_t)b * L + cb) * D_
                                          : nw + (size_t)(cb - L) * D_;

    if (tid < BM) { rsmem[tid] = 0.f; csmem[tid] = 0.f; }

    // cp.async slots: 4 x 16B per tile per thread (1024 chunks / 256 threads)
    // chunk q: row = q>>3 (128-byte rows of data), seg = q&7
    const uint32_t asb = smem_u32(dsm);                       // A stages 0..1
    const uint32_t bsb = asb + NSTAGE * TILEB;                // B stages 0..1
    uint32_t sA[4], sB[4];
    uint32_t gofs[4];
    #pragma unroll
    for (int j = 0; j < 4; j++) {
        int q = tid + 256 * j;
        int row = q >> 3, seg = q & 7;
        sA[j] = asb + row * SROW + seg * 16;
        sB[j] = bsb + row * SROW + seg * 16;
        gofs[j] = (uint32_t)row * D_ + seg * 8;   // elements
    }

    // ldmatrix base addresses (stage offset + kk added in loop)
    uint32_t aAddr[2], bAddr[4];
    {
        const int arow = (lane & 15), ach = (lane >> 4) * 8;
        #pragma unroll
        for (int mi = 0; mi < 2; mi++)
            aAddr[mi] = asb + (warpM * 32 + mi * 16 + arow) * SROW + ach * 2;
        const int bn = (lane & 7) + ((lane >> 4) & 1) * 8;
        const int bkh = ((lane >> 3) & 1) * 8;
        #pragma unroll
        for (int pr = 0; pr < 4; pr++)
            bAddr[pr] = bsb + (warpN * 64 + pr * 16 + bn) * SROW + bkh * 2;
    }

    float acc[2][8][4];
    #pragma unroll
    for (int mi = 0; mi < 2; mi++)
        #pragma unroll
        for (int ni = 0; ni < 8; ni++)
            #pragma unroll
            for (int r = 0; r < 4; r++) acc[mi][ni][r] = 0.f;

    auto load_stage = [&](int st, int kt) {
        const uint32_t so = (uint32_t)st * TILEB;
        const int kb = kt * BK;
        #pragma unroll
        for (int j = 0; j < 4; j++) {
            cp_async16(sA[j] + so, baseA + gofs[j] + kb);
            cp_async16(sB[j] + so, baseB + gofs[j] + kb);
        }
        cp_commit();
    };

    load_stage(0, 0);
    load_stage(1, 1);

    int st = 0;
    #pragma unroll 1
    for (int kt = 0; kt < NKT; ++kt) {
        if (kt == NKT - 1) cp_wait<0>(); else cp_wait<1>();
        __syncthreads();   // stage st visible; stage st^1 drained before next overwrite
        if (kt + 2 < NKT) load_stage(st ^ 1, kt + 2);

        const uint32_t bofs = (uint32_t)st * TILEB;
        #pragma unroll
        for (int kk = 0; kk < BK; kk += 16) {
            uint32_t af[2][4];
            ldsm_x4(af[0], aAddr[0] + bofs + kk * 2);
            ldsm_x4(af[1], aAddr[1] + bofs + kk * 2);
            #pragma unroll
            for (int pr = 0; pr < 4; pr++) {
                uint32_t bf[4];
                ldsm_x4(bf, bAddr[pr] + bofs + kk * 2);
                mma_bf16(acc[0][pr * 2    ], af[0][0], af[0][1], af[0][2], af[0][3], bf[0], bf[1]);
                mma_bf16(acc[1][pr * 2    ], af[1][0], af[1][1], af[1][2], af[1][3], bf[0], bf[1]);
                mma_bf16(acc[0][pr * 2 + 1], af[0][0], af[0][1], af[0][2], af[0][3], bf[2], bf[3]);
                mma_bf16(acc[1][pr * 2 + 1], af[1][0], af[1][1], af[1][2], af[1][3], bf[2], bf[3]);
            }
        }
        if (kt + 1 < NKT) __syncthreads();   // all warps done with stage st before its overwrite
        st ^= 1;
    }

    // ---- epilogue: e = 4096*exp(s-10) = 2^(a*C2 + CS) via ex2.approx.f16x2 ----
    const float C2 = 14.4269504089f;    // 10*log2(e)
    const float CS = -2.4269504089f;    // -C2 + 12 (x2^12 keeps f16 normal)
    const int qrow = lane >> 2;
    float colS[8][2];
    #pragma unroll
    for (int ni = 0; ni < 8; ni++) { colS[ni][0] = 0.f; colS[ni][1] = 0.f; }

    #pragma unroll
    for (int mi = 0; mi < 2; mi++) {
        #pragma unroll
        for (int h = 0; h < 2; h++) {
            const int lrow = warpM * 32 + mi * 16 + h * 8 + qrow;
            float rs = 0.f;
            #pragma unroll
            for (int ni = 0; ni < 8; ni++) {
                float x0 = fmaf(acc[mi][ni][h * 2 + 0], C2, CS);
                float x1 = fmaf(acc[mi][ni][h * 2 + 1], C2, CS);
                __half2 he = h2exp2(__floats2half2_rn(x0, x1));
                float2 ef = __half22float2(he);
                if (diag) {
                    const int lcol0 = warpN * 64 + ni * 8 + (lane & 3) * 2;
                    if (lcol0     == lrow) ef.x = 4096.0f;   // exact diagonal exp(0)*2^12
                    if (lcol0 + 1 == lrow) ef.y = 4096.0f;
                } else {
                    colS[ni][0] += ef.x;
                    colS[ni][1] += ef.y;
                }
                rs += ef.x + ef.y;
            }
            rs += __shfl_xor_sync(0xffffffffu, rs, 1);
            rs += __shfl_xor_sync(0xffffffffu, rs, 2);
            if ((lane & 3) == 0) atomicAdd(&rsmem[lrow], rs);
        }
    }
    if (!diag) {
        #pragma unroll
        for (int ni = 0; ni < 8; ni++) {
            #pragma unroll
            for (int c = 0; c < 2; c++) {
                float v = colS[ni][c];
                v += __shfl_xor_sync(0xffffffffu, v, 4);
                v += __shfl_xor_sync(0xffffffffu, v, 8);
                v += __shfl_xor_sync(0xffffffffu, v, 16);
                if (qrow == 0) {
                    const int lcol = warpN * 64 + ni * 8 + (lane & 3) * 2 + c;
                    atomicAdd(&csmem[lcol], v);
                }
            }
        }
    }

    __syncthreads();
    if (tid < BM) {
        if (ww) {
            g_wwsum[S][tid] = rsmem[tid];       // written once (b==0 job only)
        } else {
            atomicAdd(gsum + rb + tid, rsmem[tid]);
            if (!diag) atomicAdd(gsum + cb + tid, csmem[tid]);
        }
    }
}

// ---------------- per-(b,scale) loss reduction + fused finalize (ticket) ----------------
__global__ void __launch_bounds__(256)
reduce_kernel(float* out_loss)
{
    const int b = blockIdx.x, S = blockIdx.y, tid = threadIdx.x;
    const int N = S ? N1_ : N0_;
    const int H = S ? H1_ : H0_;
    const int L = S ? L1_ : L0_;
    const float* gsum = g_gsum + (S ? B_ * N0_ : 0) + (size_t)b * N;
    const int* cnt = S ? g_cnt1 : g_cnt0;
    const float* posg = g_posg + b * HT_ + (S ? H0_ : 0);

    const float LOGSC = 8.3177661667f;   // ln(4096)
    float local = 0.f;
    for (int n = tid; n < N; n += 256) {
        if (cnt[n] > 0) {
            float rs = gsum[n];
            if (n >= L) rs += g_wwsum[S][n - L];    // batch-invariant word-word part
            local += 10.0f + __logf(rs) - LOGSC;
        }
    }
    for (int k = tid; k < H; k += 256) local -= posg[k];

    #pragma unroll
    for (int o = 16; o > 0; o >>= 1) local += __shfl_down_sync(0xffffffffu, local, o);
    __shared__ float sp[8];
    if ((tid & 31) == 0) sp[tid >> 5] = local;
    __syncthreads();
    if (tid == 0) {
        float t = 0.f;
        #pragma unroll
        for (int i = 0; i < 8; i++) t += sp[i];
        atomicAdd(&g_loss[S], (double)t);
        __threadfence();
        int done = atomicAdd(&g_redcnt, 1);
        if (done == 2 * B_ - 1) {               // last of 128 blocks: finalize
            double l = 0.0;
            #pragma unroll
            for (int s = 0; s < 2; s++) {
                int nv = g_nvalid[s];
                if (nv > 0) l += g_loss[s] / (double)(B_ * nv);
            }
            *out_loss = (float)l;
        }
    }
}

// ---------------- launch: fork/join; side stream at LOW priority ----------------
extern "C" void kernel_launch(void* const* d_in, const int* in_sizes, int n_in,
                              void* d_out, int out_size)
{
    const float* x0   = (const float*)d_in[0];
    const float* x1   = (const float*)d_in[1];
    const float* w0   = (const float*)d_in[2];
    const float* w1   = (const float*)d_in[3];
    const float* hy0  = (const float*)d_in[4];
    const float* hy1  = (const float*)d_in[5];
    const float* nod0 = (const float*)d_in[6];
    const float* nod1 = (const float*)d_in[7];
    float* out = (float*)d_out;

    float* adj0  = out;
    float* adj1  = out + (size_t)N0_ * H0_;
    float* lossp = out + (size_t)N0_ * H0_ + (size_t)N1_ * H1_;

    static cudaStream_t s1 = nullptr;
    static cudaEvent_t ev0 = nullptr, evN = nullptr, ev1 = nullptr;
    if (s1 == nullptr) {
        int loPri = 0, hiPri = 0;
        cudaDeviceGetStreamPriorityRange(&loPri, &hiPri);   // loPri = least urgent
        cudaStreamCreateWithPriority(&s1, cudaStreamNonBlocking, loPri);
        cudaEventCreateWithFlags(&ev0, cudaEventDisableTiming);
        cudaEventCreateWithFlags(&evN, cudaEventDisableTiming);
        cudaEventCreateWithFlags(&ev1, cudaEventDisableTiming);
        cudaFuncSetAttribute(sim_kernel, cudaFuncAttributeMaxDynamicSharedMemorySize, SIM_DSMEM);
    }

    // fork: low-priority side stream runs adjacency chain, backfilling idle SMs
    cudaEventRecord(ev0, 0);
    cudaStreamWaitEvent(s1, ev0, 0);

    adjq_kernel<<<N0_ / 4 + N1_ / 4, 128, 0, s1>>>(nod0, hy0, nod1, hy1, adj0, adj1);
    cnt_kernel<<<2, 256, 0, s1>>>();

    const int nrows = B_ * L0_ + B_ * L1_ + 2 * WS_;   // 49408
    normx_kernel<<<nrows / 8, 256>>>(x0, x1, w0, w1);
    cudaEventRecord(evN, 0);

    // posg needs normx output (evN) + cnt (s1 order); backfills under sim
    cudaStreamWaitEvent(s1, evN, 0);
    posg_kernel<<<dim3(HT_, B_), 128, 0, s1>>>();
    cudaEventRecord(ev1, s1);

    sim_kernel<<<SIM_JOBS, 256, SIM_DSMEM>>>();

    // join: reduce(+finalize) needs sim (stream 0) + posg/cnt (ev1)
    cudaStreamWaitEvent(0, ev1, 0);
    reduce_kernel<<<dim3(B_, 2), 256>>>(lossp);
}

// round 17
// speedup vs baseline: 1.1400x; 1.0003x over previous
#include <cuda_runtime.h>
#include <cuda_bf16.h>
#include <cuda_fp16.h>
#include <cstdint>

// ---------------- fixed problem shape ----------------
#define B_   64
#define D_   512
#define L0_  512
#define L1_  256
#define WS_  128
#define H0_  128
#define H1_  64
#define N0_  (L0_ + WS_)   // 640
#define N1_  (L1_ + WS_)   // 384
#define HT_  (H0_ + H1_)   // 192
// triangular pairs: scale0 T=5 -> 15 (ww = idx 14), scale1 T=3 -> 6 (ww = idx 5)
#define NP0_NW 14
#define NP1_NW 5
#define SIM_JOBS (NP0_NW * B_ + NP1_NW * B_ + 2)   // 896 + 320 + 2 = 1218

// ---------------- device scratch ----------------
__device__ __nv_bfloat16 g_nx0[(size_t)B_ * L0_ * D_];
__device__ __nv_bfloat16 g_nx1[(size_t)B_ * L1_ * D_];
__device__ __nv_bfloat16 g_nw0[WS_ * D_];
__device__ __nv_bfloat16 g_nw1[WS_ * D_];
__device__ float g_selfx0[B_ * L0_];
__device__ float g_selfx1[B_ * L1_];
__device__ float g_selfw0[WS_];
__device__ float g_selfw1[WS_];
__device__ int   g_eidx0[N0_], g_eidx1[N1_];
__device__ int   g_memb0[N0_], g_memb1[N1_];
__device__ int   g_gstart0[H0_ + 1], g_gstart1[H1_ + 1];
__device__ int   g_cnt0[N0_], g_cnt1[N1_];
__device__ int   g_nvalid[2];
__device__ float g_posg[B_ * HT_];
#define GSUMTOT (B_ * (N0_ + N1_))   // 65536
__device__ float g_gsum[GSUMTOT];
__device__ float g_wwsum[2][WS_];    // batch-invariant word-word tile row sums
__device__ double g_loss[2];
__device__ int   g_redcnt;           // reduce completion ticket

// ---------------- adjacency: 4 nodes/block, both scales in one grid ----------------
// softmax row sums to 1 => at most one entry > 0.5 and it is the row max =>
// always inside top-k: adj_bin = (p > 0.5). No top-k machinery needed.
__global__ void __launch_bounds__(128)
adjq_kernel(const float* __restrict__ nod0, const float* __restrict__ hy0,
            const float* __restrict__ nod1, const float* __restrict__ hy1,
            float* __restrict__ adj0, float* __restrict__ adj1)
{
    const int blk = blockIdx.x;
    const int tid = threadIdx.x;

    const int S = (blk >= N0_ / 4);
    const int nbase = (S ? (blk - N0_ / 4) : blk) * 4;
    const int H = S ? H1_ : H0_;
    const float* enod = S ? nod1 : nod0;
    const float* ehy  = S ? hy1  : hy0;
    float* adj_out = S ? adj1 : adj0;
    int* eidx = S ? g_eidx1 : g_eidx0;

    __shared__ float xrow[4][D_];
    __shared__ float et[128][36];
    __shared__ float rbuf[128];
    __shared__ int   widx[4];

    #pragma unroll
    for (int r = 0; r < 4; r++)
        *(float4*)&xrow[r][tid * 4] = *(const float4*)(enod + (size_t)(nbase + r) * D_ + tid * 4);

    float acc[4] = {0.f, 0.f, 0.f, 0.f};
    const int nf4 = H * 8;
    for (int kk = 0; kk < D_; kk += 32) {
        __syncthreads();
        for (int f = tid; f < nf4; f += 128) {
            int h = f >> 3, c4 = f & 7;
            *(float4*)&et[h][c4 * 4] = *(const float4*)(ehy + (size_t)h * D_ + kk + c4 * 4);
        }
        __syncthreads();
        if (tid < H) {
            #pragma unroll
            for (int c4 = 0; c4 < 8; c4++) {
                float4 e4 = *(const float4*)&et[tid][c4 * 4];
                #pragma unroll
                for (int r = 0; r < 4; r++) {
                    float4 x4 = *(const float4*)&xrow[r][kk + c4 * 4];
                    acc[r] = fmaf(x4.x, e4.x, acc[r]);
                    acc[r] = fmaf(x4.y, e4.y, acc[r]);
                    acc[r] = fmaf(x4.z, e4.z, acc[r]);
                    acc[r] = fmaf(x4.w, e4.w, acc[r]);
                }
            }
        }
    }

    #pragma unroll
    for (int r = 0; r < 4; r++) {
        float z = (tid < H) ? fmaxf(3.0f * acc[r], 0.0f) : -1e30f;
        __syncthreads();
        rbuf[tid] = z; __syncthreads();
        for (int o = 64; o > 0; o >>= 1) { if (tid < o) rbuf[tid] = fmaxf(rbuf[tid], rbuf[tid + o]); __syncthreads(); }
        float zmax = rbuf[0]; __syncthreads();
        float e = (tid < H) ? __expf(z - zmax) : 0.f;
        rbuf[tid] = e; __syncthreads();
        for (int o = 64; o > 0; o >>= 1) { if (tid < o) rbuf[tid] += rbuf[tid + o]; __syncthreads(); }
        float ssum = rbuf[0];
        if (tid == 0) widx[r] = -1;
        __syncthreads();
        if (tid < H) {
            int bin = (e / ssum) > 0.5f;
            adj_out[(size_t)(nbase + r) * H + tid] = (float)bin;
            if (bin) widx[r] = tid;
        }
    }
    __syncthreads();
    if (tid < 4) eidx[nbase + tid] = widx[tid];
}

// ---------------- counts + group member lists ----------------
__global__ void __launch_bounds__(256)
cnt_kernel()
{
    const int S = blockIdx.x;
    const int N = S ? N1_ : N0_;
    const int H = S ? H1_ : H0_;
    const int* eidx = S ? g_eidx1 : g_eidx0;
    int* memb = S ? g_memb1 : g_memb0;
    int* gst  = S ? g_gstart1 : g_gstart0;
    int* cnt  = S ? g_cnt1 : g_cnt0;

    __shared__ int sz[128];
    __shared__ int scanb[128];
    __shared__ int cur[128];
    __shared__ int vc;
    const int tid = threadIdx.x;
    if (tid < H) sz[tid] = 0;
    if (tid == 0) vc = 0;
    __syncthreads();
    for (int n = tid; n < N; n += 256) {
        int e = eidx[n];
        if (e >= 0) atomicAdd(&sz[e], 1);
    }
    __syncthreads();
    if (tid < H) scanb[tid] = sz[tid];
    __syncthreads();
    for (int o = 1; o < H; o <<= 1) {
        int v = (tid < H && tid >= o) ? scanb[tid - o] : 0;
        __syncthreads();
        if (tid < H) scanb[tid] += v;
        __syncthreads();
    }
    if (tid < H) { gst[tid] = scanb[tid] - sz[tid]; cur[tid] = scanb[tid] - sz[tid]; }
    if (tid == 0) gst[H] = scanb[H - 1];
    __syncthreads();
    int local = 0;
    for (int n = tid; n < N; n += 256) {
        int e = eidx[n];
        int c = 0;
        if (e >= 0) {
            int p = atomicAdd(&cur[e], 1);
            memb[p] = n;
            c = sz[e] - 1;
        }
        cnt[n] = c;
        if (c > 0) local++;
    }
    atomicAdd(&vc, local);
    __syncthreads();
    if (tid == 0) g_nvalid[S] = vc;
}

// ---------------- normalize -> bf16 + self-dot (+ fused accumulator init) ----------------
__global__ void __launch_bounds__(256)
normx_kernel(const float* __restrict__ x0, const float* __restrict__ x1,
             const float* __restrict__ w0, const float* __restrict__ w1)
{
    // fused init: zero g_gsum / g_loss / ticket (graph replays re-run every launch)
    if (blockIdx.x < GSUMTOT / 256) {
        int gid = blockIdx.x * 256 + threadIdx.x;
        g_gsum[gid] = 0.f;
        if (gid == 0) { g_loss[0] = 0.0; g_loss[1] = 0.0; g_redcnt = 0; }
    }

    const int gw   = (blockIdx.x * 256 + threadIdx.x) >> 5;
    const int lane = threadIdx.x & 31;
    const float* src;
    __nv_bfloat16* dst;
    float* selfp;
    int r = gw;
    if (r < B_ * L0_)                    { src = x0 + (size_t)r * D_; dst = g_nx0 + (size_t)r * D_; selfp = g_selfx0 + r; }
    else if ((r -= B_ * L0_) < B_ * L1_) { src = x1 + (size_t)r * D_; dst = g_nx1 + (size_t)r * D_; selfp = g_selfx1 + r; }
    else if ((r -= B_ * L1_) < WS_)      { src = w0 + (size_t)r * D_; dst = g_nw0 + (size_t)r * D_; selfp = g_selfw0 + r; }
    else { r -= WS_;                       src = w1 + (size_t)r * D_; dst = g_nw1 + (size_t)r * D_; selfp = g_selfw1 + r; }

    float4 v[4];
    #pragma unroll
    for (int i = 0; i < 4; i++) v[i] = *(const float4*)(src + i * 128 + lane * 4);
    float ss = 0.f;
    #pragma unroll
    for (int i = 0; i < 4; i++) ss += v[i].x*v[i].x + v[i].y*v[i].y + v[i].z*v[i].z + v[i].w*v[i].w;
    #pragma unroll
    for (int o = 16; o > 0; o >>= 1) ss += __shfl_xor_sync(0xffffffffu, ss, o);
    float iv = 1.0f / fmaxf(sqrtf(ss), 1e-12f);
    float sd = 0.f;
    #pragma unroll
    for (int i = 0; i < 4; i++) {
        __nv_bfloat162 p0 = __floats2bfloat162_rn(v[i].x * iv, v[i].y * iv);
        __nv_bfloat162 p1 = __floats2bfloat162_rn(v[i].z * iv, v[i].w * iv);
        float2 f0 = __bfloat1622float2(p0);
        float2 f1 = __bfloat1622float2(p1);
        sd += f0.x*f0.x + f0.y*f0.y + f1.x*f1.x + f1.y*f1.y;
        uint2 pk; pk.x = *(uint32_t*)&p0; pk.y = *(uint32_t*)&p1;
        *(uint2*)(dst + i * 128 + lane * 4) = pk;
    }
    #pragma unroll
    for (int o = 16; o > 0; o >>= 1) sd += __shfl_xor_sync(0xffffffffu, sd, o);
    if (lane == 0) *selfp = sd;
}

// ---------------- per-(b,edge) positive group sums ----------------
// sum_{n!=m in group} s_nm = 10*(||sum of rows||^2 - sum selfdot); cnt within a
// group is sz-1 for all members, so loss needs only this total / (sz-1).
__global__ void __launch_bounds__(128)
posg_kernel()
{
    const int kg = blockIdx.x;
    const int S  = (kg >= H0_);
    const int k  = S ? kg - H0_ : kg;
    const int b  = blockIdx.y;
    const int tid = threadIdx.x;

    const int* gst  = S ? g_gstart1 : g_gstart0;
    const int* memb = S ? g_memb1 : g_memb0;
    const int L = S ? L1_ : L0_;
    const __nv_bfloat16* nx = S ? g_nx1 : g_nx0;
    const __nv_bfloat16* nw = S ? g_nw1 : g_nw0;
    const float* selfx = S ? g_selfx1 : g_selfx0;
    const float* selfw = S ? g_selfw1 : g_selfw0;

    const int s0 = gst[k], s1 = gst[k + 1];
    const int szk = s1 - s0;
    float* outp = &g_posg[b * HT_ + kg];
    if (szk < 2) { if (tid == 0) *outp = 0.f; return; }

    float g0 = 0.f, g1 = 0.f, g2 = 0.f, g3 = 0.f;
    float selfs = 0.f;
    for (int i = s0; i < s1; i++) {
        int n = memb[i];
        const __nv_bfloat16* row = (n < L) ? nx + ((size_t)b * L + n) * D_
                                           : nw + (size_t)(n - L) * D_;
        uint2 u = *(const uint2*)(row + tid * 4);
        __nv_bfloat162 p0 = *(__nv_bfloat162*)&u.x;
        __nv_bfloat162 p1 = *(__nv_bfloat162*)&u.y;
        float2 f0 = __bfloat1622float2(p0);
        float2 f1 = __bfloat1622float2(p1);
        g0 += f0.x; g1 += f0.y; g2 += f1.x; g3 += f1.y;
    }
    for (int i = s0 + tid; i < s1; i += 128) {
        int n = memb[i];
        selfs += (n < L) ? selfx[(size_t)b * L + n] : selfw[n - L];
    }
    float val = g0*g0 + g1*g1 + g2*g2 + g3*g3;
    #pragma unroll
    for (int o = 16; o > 0; o >>= 1) {
        val   += __shfl_xor_sync(0xffffffffu, val, o);
        selfs += __shfl_xor_sync(0xffffffffu, selfs, o);
    }
    __shared__ float sv[4], sf[4];
    if ((tid & 31) == 0) { sv[tid >> 5] = val; sf[tid >> 5] = selfs; }
    __syncthreads();
    if (tid == 0) {
        float gv = sv[0] + sv[1] + sv[2] + sv[3];
        float sc = sf[0] + sf[1] + sf[2] + sf[3];
        *outp = 10.0f * (gv - sc) / (float)(szk - 1);
    }
}

// ---------------- fused sim GEMM (bf16 mma + ldmatrix, BK=64, double buffer) ----------------
#define BM 128
#define BN 128
#define BK 64
#define SKEW 8
#define SROW ((BK + SKEW) * 2)      // 144 bytes per smem row
#define TILEB (BM * SROW)           // 18432 bytes per tile buffer
#define NKT (D_ / BK)               // 8
#define NSTAGE 2
#define SIM_DSMEM (2 * NSTAGE * TILEB)   // 73728

__device__ __forceinline__ uint32_t smem_u32(const void* p) {
    uint32_t a;
    asm("{ .reg .u64 t; cvta.to.shared.u64 t, %1; cvt.u32.u64 %0, t; }" : "=r"(a) : "l"(p));
    return a;
}
__device__ __forceinline__ void cp_async16(uint32_t saddr, const void* gptr) {
    asm volatile("cp.async.cg.shared.global [%0], [%1], 16;\n" :: "r"(saddr), "l"(gptr));
}
__device__ __forceinline__ void cp_commit() { asm volatile("cp.async.commit_group;\n"); }
template<int NN> __device__ __forceinline__ void cp_wait() {
    asm volatile("cp.async.wait_group %0;\n" :: "n"(NN));
}
__device__ __forceinline__ void ldsm_x4(uint32_t r[4], uint32_t saddr) {
    asm volatile("ldmatrix.sync.aligned.m8n8.x4.shared.b16 {%0,%1,%2,%3}, [%4];"
        : "=r"(r[0]), "=r"(r[1]), "=r"(r[2]), "=r"(r[3]) : "r"(saddr));
}
__device__ __forceinline__ void mma_bf16(float c[4],
    uint32_t a0, uint32_t a1, uint32_t a2, uint32_t a3, uint32_t b0, uint32_t b1)
{
    asm volatile("mma.sync.aligned.m16n8k16.row.col.f32.bf16.bf16.f32 "
        "{%0,%1,%2,%3}, {%4,%5,%6,%7}, {%8,%9}, {%0,%1,%2,%3};\n"
        : "+f"(c[0]), "+f"(c[1]), "+f"(c[2]), "+f"(c[3])
        : "r"(a0), "r"(a1), "r"(a2), "r"(a3), "r"(b0), "r"(b1));
}

// Flat 1-D grid of exactly SIM_JOBS useful CTAs (no early-exit holes):
//   [0, 896)        scale0 non-ww: b = g/14, p = g%14   (ww pair is triangular idx 14)
//   [896, 1216)     scale1 non-ww: b = g/5,  p = g%5    (ww pair is triangular idx 5)
//   1216            scale0 ww (p=14, b=0)
//   1217            scale1 ww (p=5,  b=0)
__global__ void __launch_bounds__(256, 2)
sim_kernel()
{
    extern __shared__ char dsm[];
    __shared__ float rsmem[BM], csmem[BN];

    const int tid  = threadIdx.x;
    const int lane = tid & 31;
    const int warp = tid >> 5;
    const int warpM = warp >> 1;
    const int warpN = warp & 1;

    // decode packed job id
    int gid = blockIdx.x;
    int S, p, b;
    if (gid < NP0_NW * B_)            { S = 0; b = gid / NP0_NW; p = gid % NP0_NW; }
    else if ((gid -= NP0_NW * B_) < NP1_NW * B_) { S = 1; b = gid / NP1_NW; p = gid % NP1_NW; }
    else if (gid == NP1_NW * B_)      { S = 0; b = 0; p = 14; }
    else                              { S = 1; b = 0; p = 5; }

    const int T = S ? (N1_ >> 7) : (N0_ >> 7);
    int rt = 0;
    while (p >= T - rt) { p -= T - rt; rt++; }
    const int ct = rt + p;
    const bool diag = (rt == ct);

    const int rb = rt * BM, cb = ct * BN;
    const int L = S ? L1_ : L0_;
    const int N = S ? N1_ : N0_;
    const bool ww = diag && (rb >= L);       // word-word tile: batch-invariant (b==0 only in grid)

    const __nv_bfloat16* nx = S ? g_nx1 : g_nx0;
    const __nv_bfloat16* nw = S ? g_nw1 : g_nw0;
    float* gsum = g_gsum + (S ? B_ * N0_ : 0) + (size_t)b * N;

    const __nv_bfloat16* baseA = (rb < L) ? nx + ((size_t)b * L + rb) * D_
                                          : nw + (size_t)(rb - L) * D_;
    const __nv_bfloat16* baseB = (cb < L) ? nx + ((size_t)b * L + cb) * D_
                                          : nw + (size_t)(cb - L) * D_;

    if (tid < BM) { rsmem[tid] = 0.f; csmem[tid] = 0.f; }

    // cp.async slots: 4 x 16B per tile per thread (1024 chunks / 256 threads)
    const uint32_t asb = smem_u32(dsm);                       // A stages 0..1
    const uint32_t bsb = asb + NSTAGE * TILEB;                // B stages 0..1
    uint32_t sA[4], sB[4];
    uint32_t gofs[4];
    #pragma unroll
    for (int j = 0; j < 4; j++) {
        int q = tid + 256 * j;
        int row = q >> 3, seg = q & 7;
        sA[j] = asb + row * SROW + seg * 16;
        sB[j] = bsb + row * SROW + seg * 16;
        gofs[j] = (uint32_t)row * D_ + seg * 8;   // elements
    }

    // ldmatrix base addresses (stage offset + kk added in loop)
    uint32_t aAddr[2], bAddr[4];
    {
        const int arow = (lane & 15), ach = (lane >> 4) * 8;
        #pragma unroll
        for (int mi = 0; mi < 2; mi++)
            aAddr[mi] = asb + (warpM * 32 + mi * 16 + arow) * SROW + ach * 2;
        const int bn = (lane & 7) + ((lane >> 4) & 1) * 8;
        const int bkh = ((lane >> 3) & 1) * 8;
        #pragma unroll
        for (int pr = 0; pr < 4; pr++)
            bAddr[pr] = bsb + (warpN * 64 + pr * 16 + bn) * SROW + bkh * 2;
    }

    float acc[2][8][4];
    #pragma unroll
    for (int mi = 0; mi < 2; mi++)
        #pragma unroll
        for (int ni = 0; ni < 8; ni++)
            #pragma unroll
            for (int r = 0; r < 4; r++) acc[mi][ni][r] = 0.f;

    auto load_stage = [&](int st, int kt) {
        const uint32_t so = (uint32_t)st * TILEB;
        const int kb = kt * BK;
        #pragma unroll
        for (int j = 0; j < 4; j++) {
            cp_async16(sA[j] + so, baseA + gofs[j] + kb);
            cp_async16(sB[j] + so, baseB + gofs[j] + kb);
        }
        cp_commit();
    };

    load_stage(0, 0);
    load_stage(1, 1);

    int st = 0;
    #pragma unroll 1
    for (int kt = 0; kt < NKT; ++kt) {
        // groups committed so far: min(kt+2, NKT); need group kt complete.
        if (kt < NKT - 1) cp_wait<1>(); else cp_wait<0>();
        __syncthreads();   // all warps' G_kt data visible before compute

        const uint32_t bofs = (uint32_t)st * TILEB;
        #pragma unroll
        for (int kk = 0; kk < BK; kk += 16) {
            uint32_t af[2][4];
            ldsm_x4(af[0], aAddr[0] + bofs + kk * 2);
            ldsm_x4(af[1], aAddr[1] + bofs + kk * 2);
            #pragma unroll
            for (int pr = 0; pr < 4; pr++) {
                uint32_t bf[4];
                ldsm_x4(bf, bAddr[pr] + bofs + kk * 2);
                mma_bf16(acc[0][pr * 2    ], af[0][0], af[0][1], af[0][2], af[0][3], bf[0], bf[1]);
                mma_bf16(acc[1][pr * 2    ], af[1][0], af[1][1], af[1][2], af[1][3], bf[0], bf[1]);
                mma_bf16(acc[0][pr * 2 + 1], af[0][0], af[0][1], af[0][2], af[0][3], bf[2], bf[3]);
                mma_bf16(acc[1][pr * 2 + 1], af[1][0], af[1][1], af[1][2], af[1][3], bf[2], bf[3]);
            }
        }

        if (kt + 2 < NKT) {
            __syncthreads();              // stage st fully consumed by all warps
            load_stage(st, kt + 2);       // safe overwrite: prefetch into SAME stage
        }
        st ^= 1;
    }

    // ---- epilogue: e = 4096*exp(s-10) = 2^(a*C2 + CS) via ex2.approx.f16x2 ----
    const float C2 = 14.4269504089f;    // 10*log2(e)
    const float CS = -2.4269504089f;    // -C2 + 12 (x2^12 keeps f16 normal)
    const int qrow = lane >> 2;
    float colS[8][2];
    #pragma unroll
    for (int ni = 0; ni < 8; ni++) { colS[ni][0] = 0.f; colS[ni][1] = 0.f; }

    #pragma unroll
    for (int mi = 0; mi < 2; mi++) {
        #pragma unroll
        for (int h = 0; h < 2; h++) {
            const int lrow = warpM * 32 + mi * 16 + h * 8 + qrow;
            float rs = 0.f;
            #pragma unroll
            for (int ni = 0; ni < 8; ni++) {
                float x0 = fmaf(acc[mi][ni][h * 2 + 0], C2, CS);
                float x1 = fmaf(acc[mi][ni][h * 2 + 1], C2, CS);
                __half2 he = h2exp2(__floats2half2_rn(x0, x1));
                float2 ef = __half22float2(he);
                if (diag) {
                    const int lcol0 = warpN * 64 + ni * 8 + (lane & 3) * 2;
                    if (lcol0     == lrow) ef.x = 4096.0f;   // exact diagonal exp(0)*2^12
                    if (lcol0 + 1 == lrow) ef.y = 4096.0f;
                } else {
                    colS[ni][0] += ef.x;
                    colS[ni][1] += ef.y;
                }
                rs += ef.x + ef.y;
            }
            rs += __shfl_xor_sync(0xffffffffu, rs, 1);
            rs += __shfl_xor_sync(0xffffffffu, rs, 2);
            if ((lane & 3) == 0) atomicAdd(&rsmem[lrow], rs);
        }
    }
    if (!diag) {
        #pragma unroll
        for (int ni = 0; ni < 8; ni++) {
            #pragma unroll
            for (int c = 0; c < 2; c++) {
                float v = colS[ni][c];
                v += __shfl_xor_sync(0xffffffffu, v, 4);
                v += __shfl_xor_sync(0xffffffffu, v, 8);
                v += __shfl_xor_sync(0xffffffffu, v, 16);
                if (qrow == 0) {
                    const int lcol = warpN * 64 + ni * 8 + (lane & 3) * 2 + c;
                    atomicAdd(&csmem[lcol], v);
                }
            }
        }
    }

    __syncthreads();
    if (tid < BM) {
        if (ww) {
            g_wwsum[S][tid] = rsmem[tid];       // written once (b==0 job only)
        } else {
            atomicAdd(gsum + rb + tid, rsmem[tid]);
            if (!diag) atomicAdd(gsum + cb + tid, csmem[tid]);
        }
    }
}

// ---------------- per-(b,scale) loss reduction + fused finalize (ticket) ----------------
__global__ void __launch_bounds__(256)
reduce_kernel(float* out_loss)
{
    const int b = blockIdx.x, S = blockIdx.y, tid = threadIdx.x;
    const int N = S ? N1_ : N0_;
    const int H = S ? H1_ : H0_;
    const int L = S ? L1_ : L0_;
    const float* gsum = g_gsum + (S ? B_ * N0_ : 0) + (size_t)b * N;
    const int* cnt = S ? g_cnt1 : g_cnt0;
    const float* posg = g_posg + b * HT_ + (S ? H0_ : 0);

    const float LOGSC = 8.3177661667f;   // ln(4096)
    float local = 0.f;
    for (int n = tid; n < N; n += 256) {
        if (cnt[n] > 0) {
            float rs = gsum[n];
            if (n >= L) rs += g_wwsum[S][n - L];    // batch-invariant word-word part
            local += 10.0f + __logf(rs) - LOGSC;
        }
    }
    for (int k = tid; k < H; k += 256) local -= posg[k];

    #pragma unroll
    for (int o = 16; o > 0; o >>= 1) local += __shfl_down_sync(0xffffffffu, local, o);
    __shared__ float sp[8];
    if ((tid & 31) == 0) sp[tid >> 5] = local;
    __syncthreads();
    if (tid == 0) {
        float t = 0.f;
        #pragma unroll
        for (int i = 0; i < 8; i++) t += sp[i];
        atomicAdd(&g_loss[S], (double)t);
        __threadfence();
        int done = atomicAdd(&g_redcnt, 1);
        if (done == 2 * B_ - 1) {               // last of 128 blocks: finalize
            double l = 0.0;
            #pragma unroll
            for (int s = 0; s < 2; s++) {
                int nv = g_nvalid[s];
                if (nv > 0) l += g_loss[s] / (double)(B_ * nv);
            }
            *out_loss = (float)l;
        }
    }
}

// ---------------- launch: fork/join; side stream at LOW priority ----------------
extern "C" void kernel_launch(void* const* d_in, const int* in_sizes, int n_in,
                              void* d_out, int out_size)
{
    const float* x0   = (const float*)d_in[0];
    const float* x1   = (const float*)d_in[1];
    const float* w0   = (const float*)d_in[2];
    const float* w1   = (const float*)d_in[3];
    const float* hy0  = (const float*)d_in[4];
    const float* hy1  = (const float*)d_in[5];
    const float* nod0 = (const float*)d_in[6];
    const float* nod1 = (const float*)d_in[7];
    float* out = (float*)d_out;

    float* adj0  = out;
    float* adj1  = out + (size_t)N0_ * H0_;
    float* lossp = out + (size_t)N0_ * H0_ + (size_t)N1_ * H1_;

    static cudaStream_t s1 = nullptr;
    static cudaEvent_t ev0 = nullptr, evN = nullptr, ev1 = nullptr;
    if (s1 == nullptr) {
        int loPri = 0, hiPri = 0;
        cudaDeviceGetStreamPriorityRange(&loPri, &hiPri);   // loPri = least urgent
        cudaStreamCreateWithPriority(&s1, cudaStreamNonBlocking, loPri);
        cudaEventCreateWithFlags(&ev0, cudaEventDisableTiming);
        cudaEventCreateWithFlags(&evN, cudaEventDisableTiming);
        cudaEventCreateWithFlags(&ev1, cudaEventDisableTiming);
        cudaFuncSetAttribute(sim_kernel, cudaFuncAttributeMaxDynamicSharedMemorySize, SIM_DSMEM);
    }

    // fork: low-priority side stream runs adjacency chain, backfilling idle SMs
    cudaEventRecord(ev0, 0);
    cudaStreamWaitEvent(s1, ev0, 0);

    adjq_kernel<<<N0_ / 4 + N1_ / 4, 128, 0, s1>>>(nod0, hy0, nod1, hy1, adj0, adj1);
    cnt_kernel<<<2, 256, 0, s1>>>();

    const int nrows = B_ * L0_ + B_ * L1_ + 2 * WS_;   // 49408
    normx_kernel<<<nrows / 8, 256>>>(x0, x1, w0, w1);
    cudaEventRecord(evN, 0);

    // posg needs normx output (evN) + cnt (s1 order); backfills under sim
    cudaStreamWaitEvent(s1, evN, 0);
    posg_kernel<<<dim3(HT_, B_), 128, 0, s1>>>();
    cudaEventRecord(ev1, s1);

    sim_kernel<<<SIM_JOBS, 256, SIM_DSMEM>>>();

    // join: reduce(+finalize) needs sim (stream 0) + posg/cnt (ev1)
    cudaStreamWaitEvent(0, ev1, 0);
    reduce_kernel<<<dim3(B_, 2), 256>>>(lossp);
}